// round 14
// baseline (speedup 1.0000x reference)
#include <cuda_runtime.h>
#include <cuda_bf16.h>
#include <cstdint>

// Problem constants (fixed by the dataset)
#define NN 50000
#define EE 800000

// ---------------------------------------------------------------------------
// Device-global scratch (no allocations allowed)
// ---------------------------------------------------------------------------
__device__ float4 g_s1 [NN * 12];    // s1 (post-LN) per node, 48 floats
__device__ float4 g_V1 [NN * 12];    // V1_pre (unscaled) per node, 48 floats
__device__ float4 g_pre4[NN * 96];   // per-node record, 96 float4:
                                     // [0:32)  (VhG_x, VhG_y, VhG_z, P_gve[c])       c = 0..31
                                     // [32:64) (VhE_x, VhE_y, VhE_z, P_B[c])
                                     //         P_B[c] = c<16 ? P_gve[32+c] : P_ge[c-16]
                                     // [64:96) (Vmu_x, Vmu_y, Vmu_z, P_ge[16+(c&15)])
                                     //         Vmu mixed: c<16 gve m=c | c>=16 ge m=c-16
__device__ float4 g_upd[NN * 24];    // segment-sum accumulator -> later su_ln|Vu_pre
__device__ float  g_sumsq[2];
__device__ float  g_scale[2];
__device__ int    g_idx64;
__device__ unsigned g_bcnt0, g_bcnt1;

// ---------------------------------------------------------------------------
// f32x2 packed helpers (FFMA2 — PTX-only)
// ---------------------------------------------------------------------------
__device__ __forceinline__ uint64_t pk2(float lo, float hi) {
    uint64_t r; asm("mov.b64 %0, {%1, %2};" : "=l"(r) : "f"(lo), "f"(hi)); return r;
}
__device__ __forceinline__ void upk2(float& lo, float& hi, uint64_t v) {
    asm("mov.b64 {%0, %1}, %2;" : "=f"(lo), "=f"(hi) : "l"(v));
}
__device__ __forceinline__ void fma2(uint64_t& d, uint64_t a, uint64_t b) {
    asm("fma.rn.f32x2 %0, %1, %2, %0;" : "+l"(d) : "l"(a), "l"(b));
}

// ---------------------------------------------------------------------------
// idx dtype detection
// ---------------------------------------------------------------------------
__global__ void k_detect(const int* __restrict__ idx) {
    if (threadIdx.x == 0 && blockIdx.x == 0) {
        int allz = 1;
        for (int i = 1; i < 128; i += 2) allz &= (idx[i] == 0);
        g_idx64 = allz;
    }
}

__global__ void k_zero() {
    int i = blockIdx.x * blockDim.x + threadIdx.x;
    int st = gridDim.x * blockDim.x;
    float4 z = make_float4(0.f, 0.f, 0.f, 0.f);
    for (int t = i; t < NN * 24; t += st) g_upd[t] = z;
    if (i == 0) { g_sumsq[0] = 0.f; g_sumsq[1] = 0.f; g_bcnt0 = 0u; g_bcnt1 = 0u; }
}

// ---------------------------------------------------------------------------
// Kernel 1: per-node GVP(gv) + residual + LN; V1_pre; edge precomputes.
// One warp per node; last block computes scale[0].
// ---------------------------------------------------------------------------
struct NodeWS {
    float4 V0[16];
    float  x[80];     // [s0(48) | sh(32)]
    float  s1[48];
    float4 V1[16];
};

__global__ __launch_bounds__(128) void k_node1(
    const float* __restrict__ nodes,
    const float* __restrict__ gvWh,   // (32,16)
    const float* __restrict__ gvMu,   // (16,32)
    const float* __restrict__ gvWm,   // (48,80)
    const float* __restrict__ gvWb,   // (48)
    const float* __restrict__ lng, const float* __restrict__ lnb,
    const float* __restrict__ gveWh,  // (32,32)
    const float* __restrict__ geWh,   // (32,32)
    const float* __restrict__ gveMu,  // (16,32)
    const float* __restrict__ geMu,   // (16,32)
    const float* __restrict__ gveWm,  // (48,112)
    const float* __restrict__ geWm)   // (32,112)
{
    __shared__ float sWhT[16 * 32];
    __shared__ float sCgv[16 * 16];
    __shared__ float sWmT[80 * 48];
    __shared__ float sB[48], sG[48], sBe[48];
    __shared__ float sWhGn[16 * 32];
    __shared__ float sWhEn[16 * 32];
    __shared__ float sCN[16 * 32];
    __shared__ float sPmG[48 * 48];
    __shared__ float sPmE[48 * 32];
    __shared__ NodeWS ws[4];

    int tid = threadIdx.x;
    for (int i = tid; i < 512; i += 128) { int v = i >> 5, h = i & 31; sWhT[i] = gvWh[h * 16 + v]; }
    for (int i = tid; i < 3840; i += 128) { int k = i / 48, o = i % 48; sWmT[i] = gvWm[o * 80 + k]; }
    for (int i = tid; i < 48; i += 128) { sB[i] = gvWb[i]; sG[i] = lng[i]; sBe[i] = lnb[i]; }
    for (int i = tid; i < 512; i += 128) {
        int v = i >> 5, h = i & 31;
        sWhGn[i] = gveWh[h * 32 + v]; sWhEn[i] = geWh[h * 32 + v];
    }
    for (int i = tid; i < 2304; i += 128) { int k = i / 48, o = i % 48; sPmG[i] = gveWm[o * 112 + k]; }
    for (int i = tid; i < 1536; i += 128) { int k = i / 32, o = i % 32; sPmE[i] = geWm[o * 112 + k]; }
    for (int i = tid; i < 256; i += 128) {
        int v = i >> 4, m = i & 15;
        float acc = 0.f;
        for (int h = 0; h < 32; h++) acc = fmaf(gvMu[m * 32 + h], gvWh[h * 16 + v], acc);
        sCgv[i] = acc;
    }
    for (int i = tid; i < 512; i += 128) {
        int v = i >> 5, c = i & 31;
        float acc = 0.f;
        if (c < 16) for (int h = 0; h < 32; h++) acc = fmaf(gveMu[c * 32 + h], gveWh[h * 32 + v], acc);
        else        for (int h = 0; h < 32; h++) acc = fmaf(geMu[(c - 16) * 32 + h], geWh[h * 32 + v], acc);
        sCN[i] = acc;
    }
    __syncthreads();

    int warp = tid >> 5, lane = tid & 31, o1 = (lane & 15) + 32, mo = lane & 15;
    const bool lo16 = (lane < 16);
    NodeWS& W = ws[warp];
    int gw = blockIdx.x * 4 + warp, nw = gridDim.x * 4;
    float lsum = 0.f;
    float* s1g = (float*)g_s1;
    float* v1g = (float*)g_V1;

    for (int n = gw; n < NN; n += nw) {
        const float* row = nodes + (size_t)n * 96;
        for (int t = lane; t < 96; t += 32) {
            float v = row[t];
            if (t < 48) W.x[t] = v;
            else { int j = t - 48; ((float*)&W.V0[0])[(j / 3) * 4 + (j % 3)] = v; }
        }
        __syncwarp();

        float a0 = 0.f, a1 = 0.f, a2 = 0.f;
#pragma unroll
        for (int v = 0; v < 16; v++) {
            float w = sWhT[v * 32 + lane]; float4 c = W.V0[v];
            a0 = fmaf(w, c.x, a0); a1 = fmaf(w, c.y, a1); a2 = fmaf(w, c.z, a2);
        }
        W.x[48 + lane] = sqrtf(a0 * a0 + a1 * a1 + a2 * a2);

        float u0 = 0.f, u1 = 0.f, u2 = 0.f;
        if (lo16) {
#pragma unroll
            for (int v = 0; v < 16; v++) {
                float w = sCgv[v * 16 + lane]; float4 c = W.V0[v];
                u0 = fmaf(w, c.x, u0); u1 = fmaf(w, c.y, u1); u2 = fmaf(w, c.z, u2);
            }
        }
        __syncwarp();

        float acc0 = sB[lane], acc1 = sB[o1];
#pragma unroll 8
        for (int k = 0; k < 80; k++) {
            float xv = W.x[k];
            acc0 = fmaf(sWmT[k * 48 + lane], xv, acc0);
            acc1 = fmaf(sWmT[k * 48 + o1],  xv, acc1);
        }
        float su0 = fmaxf(acc0, 0.f) + W.x[lane];
        float su1 = fmaxf(acc1, 0.f) + W.x[o1];

        float s = su0 + (lo16 ? su1 : 0.f);
#pragma unroll
        for (int off = 16; off; off >>= 1) s += __shfl_xor_sync(0xffffffffu, s, off);
        float mean = s * (1.f / 48.f);
        float d0 = su0 - mean, d1 = su1 - mean;
        float q = d0 * d0 + (lo16 ? d1 * d1 : 0.f);
#pragma unroll
        for (int off = 16; off; off >>= 1) q += __shfl_xor_sync(0xffffffffu, q, off);
        float rstd = rsqrtf(q * (1.f / 48.f) + 1e-5f);
        float s1a = d0 * rstd * sG[lane] + sBe[lane];
        float s1b = d1 * rstd * sG[o1]  + sBe[o1];
        W.s1[lane] = s1a; s1g[(size_t)n * 48 + lane] = s1a;
        if (lo16) { W.s1[o1] = s1b; s1g[(size_t)n * 48 + o1] = s1b; }

        if (lo16) {
            float vn = sqrtf(u0 * u0 + u1 * u1 + u2 * u2);
            float4 c = W.V0[lane];
            float p0 = fmaf(vn, u0, c.x), p1 = fmaf(vn, u1, c.y), p2 = fmaf(vn, u2, c.z);
            lsum += p0 * p0 + p1 * p1 + p2 * p2;
            W.V1[lane] = make_float4(p0, p1, p2, 0.f);
            v1g[(size_t)n * 48 + 3 * lane + 0] = p0;
            v1g[(size_t)n * 48 + 3 * lane + 1] = p1;
            v1g[(size_t)n * 48 + 3 * lane + 2] = p2;
        }
        __syncwarp();

        // --- edge precompute record (float4 layout, MLP parts folded in .w) ---
        float gg0 = 0.f, gg1 = 0.f, gg2 = 0.f, ee0 = 0.f, ee1 = 0.f, ee2 = 0.f;
        float m0 = 0.f, m1 = 0.f, m2 = 0.f;
#pragma unroll
        for (int v = 0; v < 16; v++) {
            float4 p = W.V1[v];
            float wg = sWhGn[v * 32 + lane];
            gg0 = fmaf(wg, p.x, gg0); gg1 = fmaf(wg, p.y, gg1); gg2 = fmaf(wg, p.z, gg2);
            float we = sWhEn[v * 32 + lane];
            ee0 = fmaf(we, p.x, ee0); ee1 = fmaf(we, p.y, ee1); ee2 = fmaf(we, p.z, ee2);
            float wc = sCN[v * 32 + lane];
            m0 = fmaf(wc, p.x, m0); m1 = fmaf(wc, p.y, m1); m2 = fmaf(wc, p.z, m2);
        }
        float pg0 = 0.f, pg1 = 0.f, pe0 = 0.f;
#pragma unroll 8
        for (int k = 0; k < 48; k++) {
            float sv = W.s1[k];
            pg0 = fmaf(sPmG[k * 48 + lane], sv, pg0);
            pg1 = fmaf(sPmG[k * 48 + o1],  sv, pg1);
            pe0 = fmaf(sPmE[k * 32 + lane], sv, pe0);
        }
        float peLow  = __shfl_sync(0xffffffffu, pe0, mo);        // P_ge[c-16] for hi lanes
        float peHigh = __shfl_sync(0xffffffffu, pe0, 16 + mo);   // P_ge[16+mo]
        float4* pr4 = g_pre4 + (size_t)n * 96;
        pr4[lane]      = make_float4(gg0, gg1, gg2, pg0);
        pr4[32 + lane] = make_float4(ee0, ee1, ee2, lo16 ? pg1 : peLow);
        pr4[64 + lane] = make_float4(m0, m1, m2, peHigh);
        __syncwarp();
    }
#pragma unroll
    for (int off = 16; off; off >>= 1) lsum += __shfl_xor_sync(0xffffffffu, lsum, off);
    if (lane == 0) atomicAdd(&g_sumsq[0], lsum);

    __syncthreads();
    if (tid == 0) {
        __threadfence();
        unsigned t = atomicAdd(&g_bcnt0, 1u);
        if (t == gridDim.x - 1) {
            float ss = atomicAdd(&g_sumsq[0], 0.0f);
            g_scale[0] = rsqrtf(sqrtf(ss) * (1.f / 16.f));
        }
    }
}

// ---------------------------------------------------------------------------
// Kernel 2: per-edge double GVP (gve + ge). Warp per 8 edges (two quads).
// Phase 1 (per quad): float4 gather + fused Vh/Vmu FFMA2; norms parked in smem.
// Phase 2: one MLP over all 8 edges — weight LDS amortized 8x.
// ---------------------------------------------------------------------------
#define EDGE_SMEM 67968
// dyn smem layout (bytes):
//   [0:2048)      sC    float[512]     Cfac mixed
//   [2048:10240)  sWA   float[2048]
//   [10240:18432) sWB   float[2048]
//   [18432:26624) sWC   float[2048]
//   [26624:27008) sBA/sBB/sBC float[32] each
//   [27008:67968) per-warp (4 x 10240):
//     SE  float4[2][32]  (0)
//     VE  float4[2][48]  (1024)
//     SHG float4[2][32]  (2560)
//     SHE float4[2][32]  (3584)
//     HIJ float[8][96]   (4608)
//     EH  float[8][80]   (7680)

__global__ __launch_bounds__(128, 3) void k_edge(
    const float* __restrict__ edges,
    const void*  __restrict__ eidx,
    const float* __restrict__ gveWh, const float* __restrict__ gveMu,
    const float* __restrict__ gveWm, const float* __restrict__ gveWb,
    const float* __restrict__ geWh,  const float* __restrict__ geMu,
    const float* __restrict__ geWm,  const float* __restrict__ geWb,
    float* __restrict__ out_e)
{
    extern __shared__ char smem[];
    float* sC  = (float*)(smem);
    float* sWA = (float*)(smem + 2048);
    float* sWB = (float*)(smem + 10240);
    float* sWC = (float*)(smem + 18432);
    float* sBA = (float*)(smem + 26624);
    float* sBB = sBA + 32;
    float* sBC = sBA + 64;

    int tid = threadIdx.x;
    for (int i = tid; i < 512; i += 128) {
        int v = i >> 5, c = i & 31;
        float acc = 0.f;
        if (c < 16) for (int h = 0; h < 32; h++) acc = fmaf(gveMu[c * 32 + h], gveWh[h * 32 + 16 + v], acc);
        else        for (int h = 0; h < 32; h++) acc = fmaf(geMu[(c - 16) * 32 + h], geWh[h * 32 + 16 + v], acc);
        sC[i] = acc;
    }
    for (int i = tid; i < 2048; i += 128) {
        int k = i >> 5, c = i & 31;
        sWA[i] = gveWm[c * 112 + 48 + k];
        sWB[i] = (c < 16) ? gveWm[(32 + c) * 112 + 48 + k] : geWm[(c - 16) * 112 + 48 + k];
        sWC[i] = (c < 16) ? geWm[(16 + c) * 112 + 48 + k] : 0.f;
    }
    for (int i = tid; i < 32; i += 128) {
        sBA[i] = gveWb[i];
        sBB[i] = (i < 16) ? gveWb[32 + i] : geWb[i - 16];
        sBC[i] = (i < 16) ? geWb[16 + i] : 0.f;
    }
    __syncthreads();

    int warp = tid >> 5, lane = tid & 31, mo = lane & 15;
    const bool lo16 = (lane < 16);
    char* wb = smem + 27008 + warp * 10240;
    float4* SE  = (float4*)(wb);          // [2][32]
    float4* VE  = (float4*)(wb + 1024);   // [2][48]
    float4* SHG = (float4*)(wb + 2560);   // [2][32]
    float4* SHE = (float4*)(wb + 3584);   // [2][32]
    float*  HIJ = (float*)(wb + 4608);    // [8][96]
    float*  EH  = (float*)(wb + 7680);    // [8][80]

    // Register-cache Wh edge columns (lane = h)
    float whg[16], whe[16];
#pragma unroll
    for (int v = 0; v < 16; v++) {
        whg[v] = __ldg(&gveWh[lane * 32 + 16 + v]);
        whe[v] = __ldg(&geWh[lane * 32 + 16 + v]);
    }

    int gw = blockIdx.x * 4 + warp, nw = gridDim.x * 4;
    const float sc0 = g_scale[0];
    const uint64_t sc2 = pk2(sc0, sc0);
    const int is64 = g_idx64;
    const int* idx32 = (const int*)eidx;
    const long long* idx64 = (const long long*)eidx;
    float* updf = (float*)g_upd;
    const float4* pre4 = g_pre4;
    const float bA = sBA[lane], bB = sBB[lane], bC = sBC[lane];

    for (int p = gw; p < EE / 8; p += nw) {
        int e0 = 8 * p;
        int sN[8];
        if (is64) {
#pragma unroll
            for (int i = 0; i < 8; i++) sN[i] = (int)idx64[e0 + i];
        } else {
#pragma unroll
            for (int i = 0; i < 8; i++) sN[i] = idx32[e0 + i];
        }

        // MLP accumulators for 8 edges (filled per quad below)
        uint64_t A01[2], A23[2], B01[2], B23[2], C01[2], C23[2];

        // ============ Phase 1: per-quad gather + Vh/Vmu ============
#pragma unroll
        for (int q = 0; q < 2; q++) {
            int eb = e0 + 4 * q;
            int d0, d1, d2, d3;
            if (is64) {
                d0 = (int)idx64[EE + eb + 0]; d1 = (int)idx64[EE + eb + 1];
                d2 = (int)idx64[EE + eb + 2]; d3 = (int)idx64[EE + eb + 3];
            } else {
                d0 = idx32[EE + eb + 0]; d1 = idx32[EE + eb + 1];
                d2 = idx32[EE + eb + 2]; d3 = idx32[EE + eb + 3];
            }

            // Stage edge rows quad-packed
            const float* r0 = edges + (size_t)(eb + 0) * 80;
            const float* r1 = edges + (size_t)(eb + 1) * 80;
            const float* r2 = edges + (size_t)(eb + 2) * 80;
            const float* r3 = edges + (size_t)(eb + 3) * 80;
            for (int t = lane; t < 80; t += 32) {
                float4 v = make_float4(r0[t], r1[t], r2[t], r3[t]);
                if (t < 32) SE[q * 32 + t] = v;
                else        VE[q * 48 + t - 32] = v;
            }

            // Gather records (3 coalesced LDG.128 per record)
            const float4* R0 = pre4 + (size_t)d0 * 96;
            const float4* R1 = pre4 + (size_t)d1 * 96;
            const float4* R2 = pre4 + (size_t)d2 * 96;
            const float4* R3 = pre4 + (size_t)d3 * 96;
            float4 Ga = R0[lane], Gb = R1[lane], Gc = R2[lane], Gd = R3[lane];
            float4 Fa = R0[32 + lane], Fb = R1[32 + lane], Fc = R2[32 + lane], Fd = R3[32 + lane];
            float4 Ua = R0[64 + lane], Ub = R1[64 + lane], Uc = R2[64 + lane], Ud = R3[64 + lane];

            // MLP node parts + biases -> accumulators
            A01[q] = pk2(Ga.w + bA, Gb.w + bA); A23[q] = pk2(Gc.w + bA, Gd.w + bA);
            B01[q] = pk2(Fa.w + bB, Fb.w + bB); B23[q] = pk2(Fc.w + bB, Fd.w + bB);
            C01[q] = lo16 ? pk2(Ua.w + bC, Ub.w + bC) : 0;
            C23[q] = lo16 ? pk2(Uc.w + bC, Ud.w + bC) : 0;

            // Vh/Vmu accumulators (node parts scaled by sc0)
            uint64_t Gx01 = 0, Gy01 = 0, Gz01 = 0, Gx23 = 0, Gy23 = 0, Gz23 = 0;
            uint64_t Fx01 = 0, Fy01 = 0, Fz01 = 0, Fx23 = 0, Fy23 = 0, Fz23 = 0;
            uint64_t Ux01 = 0, Uy01 = 0, Uz01 = 0, Ux23 = 0, Uy23 = 0, Uz23 = 0;
            fma2(Gx01, pk2(Ga.x, Gb.x), sc2); fma2(Gy01, pk2(Ga.y, Gb.y), sc2); fma2(Gz01, pk2(Ga.z, Gb.z), sc2);
            fma2(Gx23, pk2(Gc.x, Gd.x), sc2); fma2(Gy23, pk2(Gc.y, Gd.y), sc2); fma2(Gz23, pk2(Gc.z, Gd.z), sc2);
            fma2(Fx01, pk2(Fa.x, Fb.x), sc2); fma2(Fy01, pk2(Fa.y, Fb.y), sc2); fma2(Fz01, pk2(Fa.z, Fb.z), sc2);
            fma2(Fx23, pk2(Fc.x, Fd.x), sc2); fma2(Fy23, pk2(Fc.y, Fd.y), sc2); fma2(Fz23, pk2(Fc.z, Fd.z), sc2);
            fma2(Ux01, pk2(Ua.x, Ub.x), sc2); fma2(Uy01, pk2(Ua.y, Ub.y), sc2); fma2(Uz01, pk2(Ua.z, Ub.z), sc2);
            fma2(Ux23, pk2(Uc.x, Ud.x), sc2); fma2(Uy23, pk2(Uc.y, Ud.y), sc2); fma2(Uz23, pk2(Uc.z, Ud.z), sc2);
            __syncwarp();

            // Fused Vh + Vmu loop over edge vectors
#pragma unroll
            for (int v = 0; v < 16; v++) {
                float4 vx = VE[q * 48 + 3 * v], vy = VE[q * 48 + 3 * v + 1], vz = VE[q * 48 + 3 * v + 2];
                uint64_t vx01 = pk2(vx.x, vx.y), vx23 = pk2(vx.z, vx.w);
                uint64_t vy01 = pk2(vy.x, vy.y), vy23 = pk2(vy.z, vy.w);
                uint64_t vz01 = pk2(vz.x, vz.y), vz23 = pk2(vz.z, vz.w);
                uint64_t wg2 = pk2(whg[v], whg[v]);
                uint64_t we2 = pk2(whe[v], whe[v]);
                float cf = sC[v * 32 + lane];
                uint64_t cf2 = pk2(cf, cf);
                fma2(Gx01, wg2, vx01); fma2(Gy01, wg2, vy01); fma2(Gz01, wg2, vz01);
                fma2(Gx23, wg2, vx23); fma2(Gy23, wg2, vy23); fma2(Gz23, wg2, vz23);
                fma2(Fx01, we2, vx01); fma2(Fy01, we2, vy01); fma2(Fz01, we2, vz01);
                fma2(Fx23, we2, vx23); fma2(Fy23, we2, vy23); fma2(Fz23, we2, vz23);
                fma2(Ux01, cf2, vx01); fma2(Uy01, cf2, vy01); fma2(Uz01, cf2, vz01);
                fma2(Ux23, cf2, vx23); fma2(Uy23, cf2, vy23); fma2(Uz23, cf2, vz23);
            }

            // Norms -> quad-packed shared
            {
                uint64_t S01 = 0, S23 = 0;
                fma2(S01, Gx01, Gx01); fma2(S01, Gy01, Gy01); fma2(S01, Gz01, Gz01);
                fma2(S23, Gx23, Gx23); fma2(S23, Gy23, Gy23); fma2(S23, Gz23, Gz23);
                float q0, q1, q2, q3;
                upk2(q0, q1, S01); upk2(q2, q3, S23);
                SHG[q * 32 + lane] = make_float4(sqrtf(q0), sqrtf(q1), sqrtf(q2), sqrtf(q3));
                uint64_t T01 = 0, T23 = 0;
                fma2(T01, Fx01, Fx01); fma2(T01, Fy01, Fy01); fma2(T01, Fz01, Fz01);
                fma2(T23, Fx23, Fx23); fma2(T23, Fy23, Fy23); fma2(T23, Fz23, Fz23);
                upk2(q0, q1, T01); upk2(q2, q3, T23);
                SHE[q * 32 + lane] = make_float4(sqrtf(q0), sqrtf(q1), sqrtf(q2), sqrtf(q3));
            }

            // Vmu output: ||Vmu||*Vmu
            {
                uint64_t S01 = 0, S23 = 0;
                fma2(S01, Ux01, Ux01); fma2(S01, Uy01, Uy01); fma2(S01, Uz01, Uz01);
                fma2(S23, Ux23, Ux23); fma2(S23, Uy23, Uy23); fma2(S23, Uz23, Uz23);
                float t0, t1, t2, t3;
                upk2(t0, t1, S01); upk2(t2, t3, S23);
                float n0 = sqrtf(t0), n1 = sqrtf(t1), n2 = sqrtf(t2), n3 = sqrtf(t3);
                float u0x, u1x, u0y, u1y, u0z, u1z, u2x, u3x, u2y, u3y, u2z, u3z;
                upk2(u0x, u1x, Ux01); upk2(u0y, u1y, Uy01); upk2(u0z, u1z, Uz01);
                upk2(u2x, u3x, Ux23); upk2(u2y, u3y, Uy23); upk2(u2z, u3z, Uz23);
                int hb = lo16 ? (48 + 3 * mo) : (32 + 3 * mo);
                float* base = lo16 ? HIJ : EH;
                int stride = lo16 ? 96 : 80;
                float* h0 = base + (q * 4 + 0) * stride + hb;
                float* h1 = base + (q * 4 + 1) * stride + hb;
                float* h2 = base + (q * 4 + 2) * stride + hb;
                float* h3 = base + (q * 4 + 3) * stride + hb;
                h0[0] = n0 * u0x; h0[1] = n0 * u0y; h0[2] = n0 * u0z;
                h1[0] = n1 * u1x; h1[1] = n1 * u1y; h1[2] = n1 * u1z;
                h2[0] = n2 * u2x; h2[1] = n2 * u2y; h2[2] = n2 * u2z;
                h3[0] = n3 * u3x; h3[1] = n3 * u3y; h3[2] = n3 * u3z;
            }
        }
        __syncwarp();

        // ============ Phase 2: one MLP over 8 edges ============
#pragma unroll 4
        for (int k = 0; k < 32; k++) {
            float wA = sWA[k * 32 + lane], wB = sWB[k * 32 + lane], wC = sWC[k * 32 + lane];
            uint64_t wA2 = pk2(wA, wA), wB2 = pk2(wB, wB), wC2 = pk2(wC, wC);
#pragma unroll
            for (int q = 0; q < 2; q++) {
                float4 x4 = SE[q * 32 + k];
                uint64_t x01 = pk2(x4.x, x4.y), x23 = pk2(x4.z, x4.w);
                fma2(A01[q], wA2, x01); fma2(A23[q], wA2, x23);
                fma2(B01[q], wB2, x01); fma2(B23[q], wB2, x23);
                fma2(C01[q], wC2, x01); fma2(C23[q], wC2, x23);
            }
        }
#pragma unroll 4
        for (int j = 0; j < 32; j++) {
            int k = 32 + j;
            float wA = sWA[k * 32 + lane], wB = sWB[k * 32 + lane], wC = sWC[k * 32 + lane];
            uint64_t wA2 = pk2(wA, wA), wB2 = pk2(wB, wB), wC2 = pk2(wC, wC);
#pragma unroll
            for (int q = 0; q < 2; q++) {
                float4 xg4 = SHG[q * 32 + j], xe4 = SHE[q * 32 + j];
                uint64_t xg01 = pk2(xg4.x, xg4.y), xg23 = pk2(xg4.z, xg4.w);
                uint64_t xe01 = pk2(xe4.x, xe4.y), xe23 = pk2(xe4.z, xe4.w);
                uint64_t xb01 = lo16 ? xg01 : xe01;
                uint64_t xb23 = lo16 ? xg23 : xe23;
                fma2(A01[q], wA2, xg01); fma2(A23[q], wA2, xg23);
                fma2(B01[q], wB2, xb01); fma2(B23[q], wB2, xb23);
                fma2(C01[q], wC2, xe01); fma2(C23[q], wC2, xe23);
            }
        }

        // ReLU + scalar staging (8 edges)
#pragma unroll
        for (int q = 0; q < 2; q++) {
            float A0, A1, A2, A3, B0, B1, B2, B3, C0, C1, C2, C3;
            upk2(A0, A1, A01[q]); upk2(A2, A3, A23[q]);
            upk2(B0, B1, B01[q]); upk2(B2, B3, B23[q]);
            upk2(C0, C1, C01[q]); upk2(C2, C3, C23[q]);
            HIJ[(q * 4 + 0) * 96 + lane] = fmaxf(A0, 0.f);
            HIJ[(q * 4 + 1) * 96 + lane] = fmaxf(A1, 0.f);
            HIJ[(q * 4 + 2) * 96 + lane] = fmaxf(A2, 0.f);
            HIJ[(q * 4 + 3) * 96 + lane] = fmaxf(A3, 0.f);
            if (lo16) {
                HIJ[(q * 4 + 0) * 96 + 32 + lane] = fmaxf(B0, 0.f);
                HIJ[(q * 4 + 1) * 96 + 32 + lane] = fmaxf(B1, 0.f);
                HIJ[(q * 4 + 2) * 96 + 32 + lane] = fmaxf(B2, 0.f);
                HIJ[(q * 4 + 3) * 96 + 32 + lane] = fmaxf(B3, 0.f);
                EH[(q * 4 + 0) * 80 + 16 + lane] = fmaxf(C0, 0.f);
                EH[(q * 4 + 1) * 80 + 16 + lane] = fmaxf(C1, 0.f);
                EH[(q * 4 + 2) * 80 + 16 + lane] = fmaxf(C2, 0.f);
                EH[(q * 4 + 3) * 80 + 16 + lane] = fmaxf(C3, 0.f);
            } else {
                EH[(q * 4 + 0) * 80 + lane - 16] = fmaxf(B0, 0.f);
                EH[(q * 4 + 1) * 80 + lane - 16] = fmaxf(B1, 0.f);
                EH[(q * 4 + 2) * 80 + lane - 16] = fmaxf(B2, 0.f);
                EH[(q * 4 + 3) * 80 + lane - 16] = fmaxf(B3, 0.f);
            }
        }
        __syncwarp();

        // Scatter hij (vector atomics) + store edge outputs
        if (lane < 24) {
#pragma unroll
            for (int i = 0; i < 8; i++)
                atomicAdd((float4*)(updf + (size_t)sN[i] * 96) + lane,
                          ((float4*)(HIJ + i * 96))[lane]);
        }
        if (lane < 20) {
#pragma unroll
            for (int i = 0; i < 8; i++)
                ((float4*)(out_e + (size_t)(e0 + i) * 80))[lane] = ((float4*)(EH + i * 80))[lane];
        }
        __syncwarp();
    }
}

// ---------------------------------------------------------------------------
// Kernel 3: per-node finalize; last block computes scale[1].
// ---------------------------------------------------------------------------
__global__ __launch_bounds__(256) void k_node2(
    const float* __restrict__ lng, const float* __restrict__ lnb)
{
    int tid = threadIdx.x, warp = tid >> 5, lane = tid & 31, o1 = (lane & 15) + 32;
    int gw = blockIdx.x * 8 + warp, nw = gridDim.x * 8;
    float lsum = 0.f;
    const float inv30 = 1.f / 30.f;
    const float sc0 = g_scale[0];
    float* upd = (float*)g_upd;
    const float* s1g = (const float*)g_s1;
    const float* v1g = (const float*)g_V1;

    for (int n = gw; n < NN; n += nw) {
        size_t b = (size_t)n * 96, bs = (size_t)n * 48;
        float su0 = upd[b + lane] * inv30 + s1g[bs + lane];
        float su1 = upd[b + o1]  * inv30 + s1g[bs + o1];
        float s = su0 + ((lane < 16) ? su1 : 0.f);
#pragma unroll
        for (int off = 16; off; off >>= 1) s += __shfl_xor_sync(0xffffffffu, s, off);
        float mean = s * (1.f / 48.f);
        float d0 = su0 - mean, d1 = su1 - mean;
        float q = d0 * d0 + ((lane < 16) ? d1 * d1 : 0.f);
#pragma unroll
        for (int off = 16; off; off >>= 1) q += __shfl_xor_sync(0xffffffffu, q, off);
        float rstd = rsqrtf(q * (1.f / 48.f) + 1e-5f);
        upd[b + lane] = d0 * rstd * __ldg(&lng[lane]) + __ldg(&lnb[lane]);
        if (lane < 16) upd[b + o1] = d1 * rstd * __ldg(&lng[o1]) + __ldg(&lnb[o1]);

        float v0 = upd[b + 48 + lane] * inv30 + v1g[bs + lane] * sc0;
        float v1 = upd[b + 48 + o1]  * inv30 + v1g[bs + o1]  * sc0;
        lsum += v0 * v0 + ((lane < 16) ? v1 * v1 : 0.f);
        upd[b + 48 + lane] = v0;
        if (lane < 16) upd[b + 48 + o1] = v1;
    }
#pragma unroll
    for (int off = 16; off; off >>= 1) lsum += __shfl_xor_sync(0xffffffffu, lsum, off);
    if (lane == 0) atomicAdd(&g_sumsq[1], lsum);

    __syncthreads();
    if (tid == 0) {
        __threadfence();
        unsigned t = atomicAdd(&g_bcnt1, 1u);
        if (t == gridDim.x - 1) {
            float ss = atomicAdd(&g_sumsq[1], 0.0f);
            g_scale[1] = rsqrtf(sqrtf(ss) * (1.f / 16.f));
        }
    }
}

// ---------------------------------------------------------------------------
// Kernel 4: final node output = node2 + node_update.
// ---------------------------------------------------------------------------
__global__ void k_node3(float* __restrict__ out) {
    int i = blockIdx.x * blockDim.x + threadIdx.x;
    int st = gridDim.x * blockDim.x;
    const float sc0 = g_scale[0], sc1 = g_scale[1];
    float4* out4 = (float4*)out;
    for (int t = i; t < NN * 24; t += st) {
        int n = t / 24, q = t - n * 24;
        float4 r = g_upd[t];
        float4 o;
        if (q < 12) {
            float4 s = g_s1[n * 12 + q];
            o = make_float4(s.x + r.x, s.y + r.y, s.z + r.z, s.w + r.w);
        } else {
            float4 v = g_V1[n * 12 + (q - 12)];
            o = make_float4(fmaf(v.x, sc0, r.x * sc1), fmaf(v.y, sc0, r.y * sc1),
                            fmaf(v.z, sc0, r.z * sc1), fmaf(v.w, sc0, r.w * sc1));
        }
        out4[t] = o;
    }
}

// ---------------------------------------------------------------------------
// Launch
// ---------------------------------------------------------------------------
extern "C" void kernel_launch(void* const* d_in, const int* in_sizes, int n_in,
                              void* d_out, int out_size) {
    const float *nodes = 0, *edges = 0;
    const void* eidx = 0;
    const float* w512[4]  = {0, 0, 0, 0}; int c512 = 0;
    const float* w1024[2] = {0, 0};       int c1024 = 0;
    const float* w48[4]   = {0, 0, 0, 0}; int c48 = 0;
    const float *gvWm = 0, *gveWm = 0, *geWm = 0, *geWb = 0;

    for (int i = 0; i < n_in; i++) {
        switch (in_sizes[i]) {
            case 4800000:  nodes = (const float*)d_in[i]; break;
            case 64000000: edges = (const float*)d_in[i]; break;
            case 1600000:  eidx = d_in[i]; break;
            case 512:  if (c512 < 4)  w512[c512++]   = (const float*)d_in[i]; break;
            case 1024: if (c1024 < 2) w1024[c1024++] = (const float*)d_in[i]; break;
            case 48:   if (c48 < 4)   w48[c48++]     = (const float*)d_in[i]; break;
            case 3840: gvWm  = (const float*)d_in[i]; break;
            case 5376: gveWm = (const float*)d_in[i]; break;
            case 3584: geWm  = (const float*)d_in[i]; break;
            case 32:   geWb  = (const float*)d_in[i]; break;
            default: break;
        }
    }
    const float* gvWh  = w512[0];
    const float* gvMu  = w512[1];
    const float* gveMu = w512[2];
    const float* geMu  = w512[3];
    const float* gveWh = w1024[0];
    const float* geWh  = w1024[1];
    const float* gvWb  = w48[0];
    const float* gveWb = w48[1];
    const float* lng   = w48[2];
    const float* lnb   = w48[3];

    float* out   = (float*)d_out;
    float* out_e = out + (size_t)NN * 96;

    static bool attr_done = false;
    if (!attr_done) {
        cudaFuncSetAttribute(k_edge, cudaFuncAttributeMaxDynamicSharedMemorySize, EDGE_SMEM);
        attr_done = true;
    }

    k_detect<<<1, 32>>>((const int*)eidx);
    k_zero<<<1184, 256>>>();
    k_node1<<<444, 128>>>(nodes, gvWh, gvMu, gvWm, gvWb, lng, lnb,
                          gveWh, geWh, gveMu, geMu, gveWm, geWm);
    k_edge<<<444, 128, EDGE_SMEM>>>(edges, eidx, gveWh, gveMu, gveWm, gveWb,
                                    geWh, geMu, geWm, geWb, out_e);
    k_node2<<<296, 256>>>(lng, lnb);
    k_node3<<<1184, 256>>>(out);
}

// round 16
// speedup vs baseline: 1.0480x; 1.0480x over previous
#include <cuda_runtime.h>
#include <cuda_bf16.h>
#include <cstdint>

// Problem constants (fixed by the dataset)
#define NN 50000
#define EE 800000

// ---------------------------------------------------------------------------
// Device-global scratch (no allocations allowed)
// ---------------------------------------------------------------------------
__device__ float4 g_s1 [NN * 12];    // s1 (post-LN) per node, 48 floats
__device__ float4 g_V1 [NN * 12];    // V1_pre (unscaled) per node, 48 floats
__device__ float4 g_pre4[NN * 96];   // per-node record, 96 float4:
                                     // [0:32)  (VhG_x, VhG_y, VhG_z, P_gve[c])       c = 0..31
                                     // [32:64) (VhE_x, VhE_y, VhE_z, P_B[c])
                                     //         P_B[c] = c<16 ? P_gve[32+c] : P_ge[c-16]
                                     // [64:96) (Vmu_x, Vmu_y, Vmu_z, P_ge[16+(c&15)])
                                     //         Vmu mixed: c<16 gve m=c | c>=16 ge m=c-16
__device__ float4 g_upd[NN * 24];    // segment-sum accumulator -> later su_ln|Vu_pre
__device__ float  g_sumsq[2];
__device__ float  g_scale[2];
__device__ int    g_idx64;
__device__ unsigned g_bcnt0, g_bcnt1;

// ---------------------------------------------------------------------------
// f32x2 packed helpers (FFMA2 — PTX-only)
// ---------------------------------------------------------------------------
__device__ __forceinline__ uint64_t pk2(float lo, float hi) {
    uint64_t r; asm("mov.b64 %0, {%1, %2};" : "=l"(r) : "f"(lo), "f"(hi)); return r;
}
__device__ __forceinline__ void upk2(float& lo, float& hi, uint64_t v) {
    asm("mov.b64 {%0, %1}, %2;" : "=f"(lo), "=f"(hi) : "l"(v));
}
__device__ __forceinline__ void fma2(uint64_t& d, uint64_t a, uint64_t b) {
    asm("fma.rn.f32x2 %0, %1, %2, %0;" : "+l"(d) : "l"(a), "l"(b));
}

// ---------------------------------------------------------------------------
// idx dtype detection
// ---------------------------------------------------------------------------
__global__ void k_detect(const int* __restrict__ idx) {
    if (threadIdx.x == 0 && blockIdx.x == 0) {
        int allz = 1;
        for (int i = 1; i < 128; i += 2) allz &= (idx[i] == 0);
        g_idx64 = allz;
    }
}

__global__ void k_zero() {
    int i = blockIdx.x * blockDim.x + threadIdx.x;
    int st = gridDim.x * blockDim.x;
    float4 z = make_float4(0.f, 0.f, 0.f, 0.f);
    for (int t = i; t < NN * 24; t += st) g_upd[t] = z;
    if (i == 0) { g_sumsq[0] = 0.f; g_sumsq[1] = 0.f; g_bcnt0 = 0u; g_bcnt1 = 0u; }
}

// ---------------------------------------------------------------------------
// Kernel 1: per-node GVP(gv) + residual + LN; V1_pre; edge precomputes.
// One warp per node; last block computes scale[0].
// ---------------------------------------------------------------------------
struct NodeWS {
    float4 V0[16];
    float  x[80];     // [s0(48) | sh(32)]
    float  s1[48];
    float4 V1[16];
};

__global__ __launch_bounds__(128) void k_node1(
    const float* __restrict__ nodes,
    const float* __restrict__ gvWh,   // (32,16)
    const float* __restrict__ gvMu,   // (16,32)
    const float* __restrict__ gvWm,   // (48,80)
    const float* __restrict__ gvWb,   // (48)
    const float* __restrict__ lng, const float* __restrict__ lnb,
    const float* __restrict__ gveWh,  // (32,32)
    const float* __restrict__ geWh,   // (32,32)
    const float* __restrict__ gveMu,  // (16,32)
    const float* __restrict__ geMu,   // (16,32)
    const float* __restrict__ gveWm,  // (48,112)
    const float* __restrict__ geWm)   // (32,112)
{
    __shared__ float sWhT[16 * 32];
    __shared__ float sCgv[16 * 16];
    __shared__ float sWmT[80 * 48];
    __shared__ float sB[48], sG[48], sBe[48];
    __shared__ float sWhGn[16 * 32];
    __shared__ float sWhEn[16 * 32];
    __shared__ float sCN[16 * 32];
    __shared__ float sPmG[48 * 48];
    __shared__ float sPmE[48 * 32];
    __shared__ NodeWS ws[4];

    int tid = threadIdx.x;
    for (int i = tid; i < 512; i += 128) { int v = i >> 5, h = i & 31; sWhT[i] = gvWh[h * 16 + v]; }
    for (int i = tid; i < 3840; i += 128) { int k = i / 48, o = i % 48; sWmT[i] = gvWm[o * 80 + k]; }
    for (int i = tid; i < 48; i += 128) { sB[i] = gvWb[i]; sG[i] = lng[i]; sBe[i] = lnb[i]; }
    for (int i = tid; i < 512; i += 128) {
        int v = i >> 5, h = i & 31;
        sWhGn[i] = gveWh[h * 32 + v]; sWhEn[i] = geWh[h * 32 + v];
    }
    for (int i = tid; i < 2304; i += 128) { int k = i / 48, o = i % 48; sPmG[i] = gveWm[o * 112 + k]; }
    for (int i = tid; i < 1536; i += 128) { int k = i / 32, o = i % 32; sPmE[i] = geWm[o * 112 + k]; }
    for (int i = tid; i < 256; i += 128) {
        int v = i >> 4, m = i & 15;
        float acc = 0.f;
        for (int h = 0; h < 32; h++) acc = fmaf(gvMu[m * 32 + h], gvWh[h * 16 + v], acc);
        sCgv[i] = acc;
    }
    for (int i = tid; i < 512; i += 128) {
        int v = i >> 5, c = i & 31;
        float acc = 0.f;
        if (c < 16) for (int h = 0; h < 32; h++) acc = fmaf(gveMu[c * 32 + h], gveWh[h * 32 + v], acc);
        else        for (int h = 0; h < 32; h++) acc = fmaf(geMu[(c - 16) * 32 + h], geWh[h * 32 + v], acc);
        sCN[i] = acc;
    }
    __syncthreads();

    int warp = tid >> 5, lane = tid & 31, o1 = (lane & 15) + 32, mo = lane & 15;
    const bool lo16 = (lane < 16);
    NodeWS& W = ws[warp];
    int gw = blockIdx.x * 4 + warp, nw = gridDim.x * 4;
    float lsum = 0.f;
    float* s1g = (float*)g_s1;
    float* v1g = (float*)g_V1;

    for (int n = gw; n < NN; n += nw) {
        const float* row = nodes + (size_t)n * 96;
        for (int t = lane; t < 96; t += 32) {
            float v = row[t];
            if (t < 48) W.x[t] = v;
            else { int j = t - 48; ((float*)&W.V0[0])[(j / 3) * 4 + (j % 3)] = v; }
        }
        __syncwarp();

        float a0 = 0.f, a1 = 0.f, a2 = 0.f;
#pragma unroll
        for (int v = 0; v < 16; v++) {
            float w = sWhT[v * 32 + lane]; float4 c = W.V0[v];
            a0 = fmaf(w, c.x, a0); a1 = fmaf(w, c.y, a1); a2 = fmaf(w, c.z, a2);
        }
        W.x[48 + lane] = sqrtf(a0 * a0 + a1 * a1 + a2 * a2);

        float u0 = 0.f, u1 = 0.f, u2 = 0.f;
        if (lo16) {
#pragma unroll
            for (int v = 0; v < 16; v++) {
                float w = sCgv[v * 16 + lane]; float4 c = W.V0[v];
                u0 = fmaf(w, c.x, u0); u1 = fmaf(w, c.y, u1); u2 = fmaf(w, c.z, u2);
            }
        }
        __syncwarp();

        float acc0 = sB[lane], acc1 = sB[o1];
#pragma unroll 8
        for (int k = 0; k < 80; k++) {
            float xv = W.x[k];
            acc0 = fmaf(sWmT[k * 48 + lane], xv, acc0);
            acc1 = fmaf(sWmT[k * 48 + o1],  xv, acc1);
        }
        float su0 = fmaxf(acc0, 0.f) + W.x[lane];
        float su1 = fmaxf(acc1, 0.f) + W.x[o1];

        float s = su0 + (lo16 ? su1 : 0.f);
#pragma unroll
        for (int off = 16; off; off >>= 1) s += __shfl_xor_sync(0xffffffffu, s, off);
        float mean = s * (1.f / 48.f);
        float d0 = su0 - mean, d1 = su1 - mean;
        float q = d0 * d0 + (lo16 ? d1 * d1 : 0.f);
#pragma unroll
        for (int off = 16; off; off >>= 1) q += __shfl_xor_sync(0xffffffffu, q, off);
        float rstd = rsqrtf(q * (1.f / 48.f) + 1e-5f);
        float s1a = d0 * rstd * sG[lane] + sBe[lane];
        float s1b = d1 * rstd * sG[o1]  + sBe[o1];
        W.s1[lane] = s1a; s1g[(size_t)n * 48 + lane] = s1a;
        if (lo16) { W.s1[o1] = s1b; s1g[(size_t)n * 48 + o1] = s1b; }

        if (lo16) {
            float vn = sqrtf(u0 * u0 + u1 * u1 + u2 * u2);
            float4 c = W.V0[lane];
            float p0 = fmaf(vn, u0, c.x), p1 = fmaf(vn, u1, c.y), p2 = fmaf(vn, u2, c.z);
            lsum += p0 * p0 + p1 * p1 + p2 * p2;
            W.V1[lane] = make_float4(p0, p1, p2, 0.f);
            v1g[(size_t)n * 48 + 3 * lane + 0] = p0;
            v1g[(size_t)n * 48 + 3 * lane + 1] = p1;
            v1g[(size_t)n * 48 + 3 * lane + 2] = p2;
        }
        __syncwarp();

        // --- edge precompute record (float4 layout, MLP parts folded in .w) ---
        float gg0 = 0.f, gg1 = 0.f, gg2 = 0.f, ee0 = 0.f, ee1 = 0.f, ee2 = 0.f;
        float m0 = 0.f, m1 = 0.f, m2 = 0.f;
#pragma unroll
        for (int v = 0; v < 16; v++) {
            float4 p = W.V1[v];
            float wg = sWhGn[v * 32 + lane];
            gg0 = fmaf(wg, p.x, gg0); gg1 = fmaf(wg, p.y, gg1); gg2 = fmaf(wg, p.z, gg2);
            float we = sWhEn[v * 32 + lane];
            ee0 = fmaf(we, p.x, ee0); ee1 = fmaf(we, p.y, ee1); ee2 = fmaf(we, p.z, ee2);
            float wc = sCN[v * 32 + lane];
            m0 = fmaf(wc, p.x, m0); m1 = fmaf(wc, p.y, m1); m2 = fmaf(wc, p.z, m2);
        }
        float pg0 = 0.f, pg1 = 0.f, pe0 = 0.f;
#pragma unroll 8
        for (int k = 0; k < 48; k++) {
            float sv = W.s1[k];
            pg0 = fmaf(sPmG[k * 48 + lane], sv, pg0);
            pg1 = fmaf(sPmG[k * 48 + o1],  sv, pg1);
            pe0 = fmaf(sPmE[k * 32 + lane], sv, pe0);
        }
        float peLow  = __shfl_sync(0xffffffffu, pe0, mo);        // P_ge[c-16] for hi lanes
        float peHigh = __shfl_sync(0xffffffffu, pe0, 16 + mo);   // P_ge[16+mo]
        float4* pr4 = g_pre4 + (size_t)n * 96;
        pr4[lane]      = make_float4(gg0, gg1, gg2, pg0);
        pr4[32 + lane] = make_float4(ee0, ee1, ee2, lo16 ? pg1 : peLow);
        pr4[64 + lane] = make_float4(m0, m1, m2, peHigh);
        __syncwarp();
    }
#pragma unroll
    for (int off = 16; off; off >>= 1) lsum += __shfl_xor_sync(0xffffffffu, lsum, off);
    if (lane == 0) atomicAdd(&g_sumsq[0], lsum);

    __syncthreads();
    if (tid == 0) {
        __threadfence();
        unsigned t = atomicAdd(&g_bcnt0, 1u);
        if (t == gridDim.x - 1) {
            float ss = atomicAdd(&g_sumsq[0], 0.0f);
            g_scale[0] = rsqrtf(sqrtf(ss) * (1.f / 16.f));
        }
    }
}

// ---------------------------------------------------------------------------
// Kernel 2: per-edge double GVP (gve + ge). Warp per 4 edges (quad).
// float4 record gather (12 LDG.128/quad, issued FIRST so edge-row staging
// hides their latency); FFMA2 everywhere; scalar weight LDS + register pk2.
// Static shared 47.1 KB -> 4 blocks/SM.
// ---------------------------------------------------------------------------
__global__ __launch_bounds__(128, 4) void k_edge(
    const float* __restrict__ edges,
    const void*  __restrict__ eidx,
    const float* __restrict__ gveWh, const float* __restrict__ gveMu,
    const float* __restrict__ gveWm, const float* __restrict__ gveWb,
    const float* __restrict__ geWh,  const float* __restrict__ geMu,
    const float* __restrict__ geWm,  const float* __restrict__ geWb,
    float* __restrict__ out_e)
{
    __shared__ float sC [512];               // [v*32+c] Cfac mixed (gve|ge)
    __shared__ float sWA[2048];              // [k*32+c] gve out c, cols 48+k
    __shared__ float sWB[2048];              // c<16 gve out 32+c | c>=16 ge out c-16
    __shared__ float sWC[2048];              // c<16 ge out 16+c | else 0
    __shared__ float sBA[32], sBB[32], sBC[32];
    __shared__ float4 sSE [4][32];           // s_e quad-packed
    __shared__ float4 sVE [4][48];           // V_e quad-packed
    __shared__ float4 sSHG[4][32], sSHE[4][32];
    __shared__ float  sHIJ[4][4][96];
    __shared__ float  sEH [4][4][80];

    int tid = threadIdx.x;
    for (int i = tid; i < 512; i += 128) {
        int v = i >> 5, c = i & 31;
        float acc = 0.f;
        if (c < 16) for (int h = 0; h < 32; h++) acc = fmaf(gveMu[c * 32 + h], gveWh[h * 32 + 16 + v], acc);
        else        for (int h = 0; h < 32; h++) acc = fmaf(geMu[(c - 16) * 32 + h], geWh[h * 32 + 16 + v], acc);
        sC[i] = acc;
    }
    for (int i = tid; i < 2048; i += 128) {
        int k = i >> 5, c = i & 31;
        sWA[i] = gveWm[c * 112 + 48 + k];
        sWB[i] = (c < 16) ? gveWm[(32 + c) * 112 + 48 + k] : geWm[(c - 16) * 112 + 48 + k];
        sWC[i] = (c < 16) ? geWm[(16 + c) * 112 + 48 + k] : 0.f;
    }
    for (int i = tid; i < 32; i += 128) {
        sBA[i] = gveWb[i];
        sBB[i] = (i < 16) ? gveWb[32 + i] : geWb[i - 16];
        sBC[i] = (i < 16) ? geWb[16 + i] : 0.f;
    }
    __syncthreads();

    int warp = tid >> 5, lane = tid & 31, mo = lane & 15;
    const bool lo16 = (lane < 16);
    float4* SE  = sSE[warp];
    float4* VE  = sVE[warp];
    float4* SHG = sSHG[warp];
    float4* SHE = sSHE[warp];
    float*  HIJ = &sHIJ[warp][0][0];
    float*  EH  = &sEH[warp][0][0];

    // Register-cache Wh edge columns (lane = h)
    float whg[16], whe[16];
#pragma unroll
    for (int v = 0; v < 16; v++) {
        whg[v] = __ldg(&gveWh[lane * 32 + 16 + v]);
        whe[v] = __ldg(&geWh[lane * 32 + 16 + v]);
    }

    int gw = blockIdx.x * 4 + warp, nw = gridDim.x * 4;
    const float sc0 = g_scale[0];
    const uint64_t sc2 = pk2(sc0, sc0);
    const int is64 = g_idx64;
    const int* idx32 = (const int*)eidx;
    const long long* idx64 = (const long long*)eidx;
    float* updf = (float*)g_upd;
    const float4* pre4 = g_pre4;
    const float bA = sBA[lane], bB = sBB[lane], bC = sBC[lane];

    for (int p = gw; p < EE / 4; p += nw) {
        int e0 = 4 * p;
        int sN[4], dN[4];
        if (is64) {
#pragma unroll
            for (int i = 0; i < 4; i++) { sN[i] = (int)idx64[e0 + i]; dN[i] = (int)idx64[EE + e0 + i]; }
        } else {
#pragma unroll
            for (int i = 0; i < 4; i++) { sN[i] = idx32[e0 + i]; dN[i] = idx32[EE + e0 + i]; }
        }

        // --- Issue record gather FIRST (12 LDG.128); staging below hides latency ---
        const float4* R0 = pre4 + (size_t)dN[0] * 96;
        const float4* R1 = pre4 + (size_t)dN[1] * 96;
        const float4* R2 = pre4 + (size_t)dN[2] * 96;
        const float4* R3 = pre4 + (size_t)dN[3] * 96;
        float4 Ga = R0[lane], Gb = R1[lane], Gc = R2[lane], Gd = R3[lane];
        float4 Fa = R0[32 + lane], Fb = R1[32 + lane], Fc = R2[32 + lane], Fd = R3[32 + lane];
        float4 Ua = R0[64 + lane], Ub = R1[64 + lane], Uc = R2[64 + lane], Ud = R3[64 + lane];

        // Stage edge rows quad-packed (overlaps record gather latency)
        const float* r0 = edges + (size_t)(e0 + 0) * 80;
        const float* r1 = edges + (size_t)(e0 + 1) * 80;
        const float* r2 = edges + (size_t)(e0 + 2) * 80;
        const float* r3 = edges + (size_t)(e0 + 3) * 80;
        for (int t = lane; t < 80; t += 32) {
            float4 v = make_float4(r0[t], r1[t], r2[t], r3[t]);
            if (t < 32) SE[t] = v;
            else        VE[t - 32] = v;
        }

        // MLP node parts + biases -> accumulators
        uint64_t A01 = pk2(Ga.w + bA, Gb.w + bA), A23 = pk2(Gc.w + bA, Gd.w + bA);
        uint64_t B01 = pk2(Fa.w + bB, Fb.w + bB), B23 = pk2(Fc.w + bB, Fd.w + bB);
        uint64_t C01 = lo16 ? pk2(Ua.w + bC, Ub.w + bC) : 0;
        uint64_t C23 = lo16 ? pk2(Uc.w + bC, Ud.w + bC) : 0;

        // Vh/Vmu accumulators (node parts scaled by sc0)
        uint64_t Gx01 = 0, Gy01 = 0, Gz01 = 0, Gx23 = 0, Gy23 = 0, Gz23 = 0;
        uint64_t Fx01 = 0, Fy01 = 0, Fz01 = 0, Fx23 = 0, Fy23 = 0, Fz23 = 0;
        uint64_t Ux01 = 0, Uy01 = 0, Uz01 = 0, Ux23 = 0, Uy23 = 0, Uz23 = 0;
        fma2(Gx01, pk2(Ga.x, Gb.x), sc2); fma2(Gy01, pk2(Ga.y, Gb.y), sc2); fma2(Gz01, pk2(Ga.z, Gb.z), sc2);
        fma2(Gx23, pk2(Gc.x, Gd.x), sc2); fma2(Gy23, pk2(Gc.y, Gd.y), sc2); fma2(Gz23, pk2(Gc.z, Gd.z), sc2);
        fma2(Fx01, pk2(Fa.x, Fb.x), sc2); fma2(Fy01, pk2(Fa.y, Fb.y), sc2); fma2(Fz01, pk2(Fa.z, Fb.z), sc2);
        fma2(Fx23, pk2(Fc.x, Fd.x), sc2); fma2(Fy23, pk2(Fc.y, Fd.y), sc2); fma2(Fz23, pk2(Fc.z, Fd.z), sc2);
        fma2(Ux01, pk2(Ua.x, Ub.x), sc2); fma2(Uy01, pk2(Ua.y, Ub.y), sc2); fma2(Uz01, pk2(Ua.z, Ub.z), sc2);
        fma2(Ux23, pk2(Uc.x, Ud.x), sc2); fma2(Uy23, pk2(Uc.y, Ud.y), sc2); fma2(Uz23, pk2(Uc.z, Ud.z), sc2);
        __syncwarp();

        // Fused Vh + Vmu loop over edge vectors (FFMA2, quad)
#pragma unroll
        for (int v = 0; v < 16; v++) {
            float4 vx = VE[3 * v], vy = VE[3 * v + 1], vz = VE[3 * v + 2];
            uint64_t vx01 = pk2(vx.x, vx.y), vx23 = pk2(vx.z, vx.w);
            uint64_t vy01 = pk2(vy.x, vy.y), vy23 = pk2(vy.z, vy.w);
            uint64_t vz01 = pk2(vz.x, vz.y), vz23 = pk2(vz.z, vz.w);
            uint64_t wg2 = pk2(whg[v], whg[v]);
            uint64_t we2 = pk2(whe[v], whe[v]);
            float cf = sC[v * 32 + lane];
            uint64_t cf2 = pk2(cf, cf);
            fma2(Gx01, wg2, vx01); fma2(Gy01, wg2, vy01); fma2(Gz01, wg2, vz01);
            fma2(Gx23, wg2, vx23); fma2(Gy23, wg2, vy23); fma2(Gz23, wg2, vz23);
            fma2(Fx01, we2, vx01); fma2(Fy01, we2, vy01); fma2(Fz01, we2, vz01);
            fma2(Fx23, we2, vx23); fma2(Fy23, we2, vy23); fma2(Fz23, we2, vz23);
            fma2(Ux01, cf2, vx01); fma2(Uy01, cf2, vy01); fma2(Uz01, cf2, vz01);
            fma2(Ux23, cf2, vx23); fma2(Uy23, cf2, vy23); fma2(Uz23, cf2, vz23);
        }

        // Norms -> quad-packed shared
        {
            uint64_t S01 = 0, S23 = 0;
            fma2(S01, Gx01, Gx01); fma2(S01, Gy01, Gy01); fma2(S01, Gz01, Gz01);
            fma2(S23, Gx23, Gx23); fma2(S23, Gy23, Gy23); fma2(S23, Gz23, Gz23);
            float q0, q1, q2, q3;
            upk2(q0, q1, S01); upk2(q2, q3, S23);
            SHG[lane] = make_float4(sqrtf(q0), sqrtf(q1), sqrtf(q2), sqrtf(q3));
            uint64_t T01 = 0, T23 = 0;
            fma2(T01, Fx01, Fx01); fma2(T01, Fy01, Fy01); fma2(T01, Fz01, Fz01);
            fma2(T23, Fx23, Fx23); fma2(T23, Fy23, Fy23); fma2(T23, Fz23, Fz23);
            upk2(q0, q1, T01); upk2(q2, q3, T23);
            SHE[lane] = make_float4(sqrtf(q0), sqrtf(q1), sqrtf(q2), sqrtf(q3));
        }

        // Vmu output: ||Vmu||*Vmu (norm >= 0 so relu is identity)
        {
            uint64_t S01 = 0, S23 = 0;
            fma2(S01, Ux01, Ux01); fma2(S01, Uy01, Uy01); fma2(S01, Uz01, Uz01);
            fma2(S23, Ux23, Ux23); fma2(S23, Uy23, Uy23); fma2(S23, Uz23, Uz23);
            float t0, t1, t2, t3;
            upk2(t0, t1, S01); upk2(t2, t3, S23);
            float n0 = sqrtf(t0), n1 = sqrtf(t1), n2 = sqrtf(t2), n3 = sqrtf(t3);
            float u0x, u1x, u0y, u1y, u0z, u1z, u2x, u3x, u2y, u3y, u2z, u3z;
            upk2(u0x, u1x, Ux01); upk2(u0y, u1y, Uy01); upk2(u0z, u1z, Uz01);
            upk2(u2x, u3x, Ux23); upk2(u2y, u3y, Uy23); upk2(u2z, u3z, Uz23);
            int hb = lo16 ? (48 + 3 * mo) : (32 + 3 * mo);
            float* base = lo16 ? HIJ : EH;
            int stride = lo16 ? 96 : 80;
            float* h0 = base + 0 * stride + hb;
            float* h1 = base + 1 * stride + hb;
            float* h2 = base + 2 * stride + hb;
            float* h3 = base + 3 * stride + hb;
            h0[0] = n0 * u0x; h0[1] = n0 * u0y; h0[2] = n0 * u0z;
            h1[0] = n1 * u1x; h1[1] = n1 * u1y; h1[2] = n1 * u1z;
            h2[0] = n2 * u2x; h2[1] = n2 * u2y; h2[2] = n2 * u2z;
            h3[0] = n3 * u3x; h3[1] = n3 * u3y; h3[2] = n3 * u3z;
        }

        // MLP: s_e half (no sync needed yet)
#pragma unroll 8
        for (int k = 0; k < 32; k++) {
            float4 x4 = SE[k];
            uint64_t x01 = pk2(x4.x, x4.y), x23 = pk2(x4.z, x4.w);
            float wA = sWA[k * 32 + lane], wB = sWB[k * 32 + lane], wC = sWC[k * 32 + lane];
            uint64_t wA2 = pk2(wA, wA), wB2 = pk2(wB, wB), wC2 = pk2(wC, wC);
            fma2(A01, wA2, x01); fma2(A23, wA2, x23);
            fma2(B01, wB2, x01); fma2(B23, wB2, x23);
            fma2(C01, wC2, x01); fma2(C23, wC2, x23);
        }
        __syncwarp();  // SHG/SHE writes visible before broadcast reads
#pragma unroll 8
        for (int j = 0; j < 32; j++) {
            int k = 32 + j;
            float4 xg4 = SHG[j], xe4 = SHE[j];
            uint64_t xg01 = pk2(xg4.x, xg4.y), xg23 = pk2(xg4.z, xg4.w);
            uint64_t xe01 = pk2(xe4.x, xe4.y), xe23 = pk2(xe4.z, xe4.w);
            uint64_t xb01 = lo16 ? xg01 : xe01;
            uint64_t xb23 = lo16 ? xg23 : xe23;
            float wA = sWA[k * 32 + lane], wB = sWB[k * 32 + lane], wC = sWC[k * 32 + lane];
            uint64_t wA2 = pk2(wA, wA), wB2 = pk2(wB, wB), wC2 = pk2(wC, wC);
            fma2(A01, wA2, xg01); fma2(A23, wA2, xg23);
            fma2(B01, wB2, xb01); fma2(B23, wB2, xb23);
            fma2(C01, wC2, xe01); fma2(C23, wC2, xe23);
        }

        // ReLU + scalar staging
        {
            float A0, A1, A2, A3, B0, B1, B2, B3, C0, C1, C2, C3;
            upk2(A0, A1, A01); upk2(A2, A3, A23);
            upk2(B0, B1, B01); upk2(B2, B3, B23);
            upk2(C0, C1, C01); upk2(C2, C3, C23);
            HIJ[0 * 96 + lane] = fmaxf(A0, 0.f);
            HIJ[1 * 96 + lane] = fmaxf(A1, 0.f);
            HIJ[2 * 96 + lane] = fmaxf(A2, 0.f);
            HIJ[3 * 96 + lane] = fmaxf(A3, 0.f);
            if (lo16) {
                HIJ[0 * 96 + 32 + lane] = fmaxf(B0, 0.f);
                HIJ[1 * 96 + 32 + lane] = fmaxf(B1, 0.f);
                HIJ[2 * 96 + 32 + lane] = fmaxf(B2, 0.f);
                HIJ[3 * 96 + 32 + lane] = fmaxf(B3, 0.f);
                EH[0 * 80 + 16 + lane] = fmaxf(C0, 0.f);
                EH[1 * 80 + 16 + lane] = fmaxf(C1, 0.f);
                EH[2 * 80 + 16 + lane] = fmaxf(C2, 0.f);
                EH[3 * 80 + 16 + lane] = fmaxf(C3, 0.f);
            } else {
                EH[0 * 80 + lane - 16] = fmaxf(B0, 0.f);
                EH[1 * 80 + lane - 16] = fmaxf(B1, 0.f);
                EH[2 * 80 + lane - 16] = fmaxf(B2, 0.f);
                EH[3 * 80 + lane - 16] = fmaxf(B3, 0.f);
            }
        }
        __syncwarp();

        // Scatter hij (vector atomics) + store edge outputs
        if (lane < 24) {
#pragma unroll
            for (int i = 0; i < 4; i++)
                atomicAdd((float4*)(updf + (size_t)sN[i] * 96) + lane,
                          ((float4*)(HIJ + i * 96))[lane]);
        }
        if (lane < 20) {
#pragma unroll
            for (int i = 0; i < 4; i++)
                ((float4*)(out_e + (size_t)(e0 + i) * 80))[lane] = ((float4*)(EH + i * 80))[lane];
        }
        __syncwarp();
    }
}

// ---------------------------------------------------------------------------
// Kernel 3: per-node finalize; last block computes scale[1].
// ---------------------------------------------------------------------------
__global__ __launch_bounds__(256) void k_node2(
    const float* __restrict__ lng, const float* __restrict__ lnb)
{
    int tid = threadIdx.x, warp = tid >> 5, lane = tid & 31, o1 = (lane & 15) + 32;
    int gw = blockIdx.x * 8 + warp, nw = gridDim.x * 8;
    float lsum = 0.f;
    const float inv30 = 1.f / 30.f;
    const float sc0 = g_scale[0];
    float* upd = (float*)g_upd;
    const float* s1g = (const float*)g_s1;
    const float* v1g = (const float*)g_V1;

    for (int n = gw; n < NN; n += nw) {
        size_t b = (size_t)n * 96, bs = (size_t)n * 48;
        float su0 = upd[b + lane] * inv30 + s1g[bs + lane];
        float su1 = upd[b + o1]  * inv30 + s1g[bs + o1];
        float s = su0 + ((lane < 16) ? su1 : 0.f);
#pragma unroll
        for (int off = 16; off; off >>= 1) s += __shfl_xor_sync(0xffffffffu, s, off);
        float mean = s * (1.f / 48.f);
        float d0 = su0 - mean, d1 = su1 - mean;
        float q = d0 * d0 + ((lane < 16) ? d1 * d1 : 0.f);
#pragma unroll
        for (int off = 16; off; off >>= 1) q += __shfl_xor_sync(0xffffffffu, q, off);
        float rstd = rsqrtf(q * (1.f / 48.f) + 1e-5f);
        upd[b + lane] = d0 * rstd * __ldg(&lng[lane]) + __ldg(&lnb[lane]);
        if (lane < 16) upd[b + o1] = d1 * rstd * __ldg(&lng[o1]) + __ldg(&lnb[o1]);

        float v0 = upd[b + 48 + lane] * inv30 + v1g[bs + lane] * sc0;
        float v1 = upd[b + 48 + o1]  * inv30 + v1g[bs + o1]  * sc0;
        lsum += v0 * v0 + ((lane < 16) ? v1 * v1 : 0.f);
        upd[b + 48 + lane] = v0;
        if (lane < 16) upd[b + 48 + o1] = v1;
    }
#pragma unroll
    for (int off = 16; off; off >>= 1) lsum += __shfl_xor_sync(0xffffffffu, lsum, off);
    if (lane == 0) atomicAdd(&g_sumsq[1], lsum);

    __syncthreads();
    if (tid == 0) {
        __threadfence();
        unsigned t = atomicAdd(&g_bcnt1, 1u);
        if (t == gridDim.x - 1) {
            float ss = atomicAdd(&g_sumsq[1], 0.0f);
            g_scale[1] = rsqrtf(sqrtf(ss) * (1.f / 16.f));
        }
    }
}

// ---------------------------------------------------------------------------
// Kernel 4: final node output = node2 + node_update.
// ---------------------------------------------------------------------------
__global__ void k_node3(float* __restrict__ out) {
    int i = blockIdx.x * blockDim.x + threadIdx.x;
    int st = gridDim.x * blockDim.x;
    const float sc0 = g_scale[0], sc1 = g_scale[1];
    float4* out4 = (float4*)out;
    for (int t = i; t < NN * 24; t += st) {
        int n = t / 24, q = t - n * 24;
        float4 r = g_upd[t];
        float4 o;
        if (q < 12) {
            float4 s = g_s1[n * 12 + q];
            o = make_float4(s.x + r.x, s.y + r.y, s.z + r.z, s.w + r.w);
        } else {
            float4 v = g_V1[n * 12 + (q - 12)];
            o = make_float4(fmaf(v.x, sc0, r.x * sc1), fmaf(v.y, sc0, r.y * sc1),
                            fmaf(v.z, sc0, r.z * sc1), fmaf(v.w, sc0, r.w * sc1));
        }
        out4[t] = o;
    }
}

// ---------------------------------------------------------------------------
// Launch
// ---------------------------------------------------------------------------
extern "C" void kernel_launch(void* const* d_in, const int* in_sizes, int n_in,
                              void* d_out, int out_size) {
    const float *nodes = 0, *edges = 0;
    const void* eidx = 0;
    const float* w512[4]  = {0, 0, 0, 0}; int c512 = 0;
    const float* w1024[2] = {0, 0};       int c1024 = 0;
    const float* w48[4]   = {0, 0, 0, 0}; int c48 = 0;
    const float *gvWm = 0, *gveWm = 0, *geWm = 0, *geWb = 0;

    for (int i = 0; i < n_in; i++) {
        switch (in_sizes[i]) {
            case 4800000:  nodes = (const float*)d_in[i]; break;
            case 64000000: edges = (const float*)d_in[i]; break;
            case 1600000:  eidx = d_in[i]; break;
            case 512:  if (c512 < 4)  w512[c512++]   = (const float*)d_in[i]; break;
            case 1024: if (c1024 < 2) w1024[c1024++] = (const float*)d_in[i]; break;
            case 48:   if (c48 < 4)   w48[c48++]     = (const float*)d_in[i]; break;
            case 3840: gvWm  = (const float*)d_in[i]; break;
            case 5376: gveWm = (const float*)d_in[i]; break;
            case 3584: geWm  = (const float*)d_in[i]; break;
            case 32:   geWb  = (const float*)d_in[i]; break;
            default: break;
        }
    }
    const float* gvWh  = w512[0];
    const float* gvMu  = w512[1];
    const float* gveMu = w512[2];
    const float* geMu  = w512[3];
    const float* gveWh = w1024[0];
    const float* geWh  = w1024[1];
    const float* gvWb  = w48[0];
    const float* gveWb = w48[1];
    const float* lng   = w48[2];
    const float* lnb   = w48[3];

    float* out   = (float*)d_out;
    float* out_e = out + (size_t)NN * 96;

    k_detect<<<1, 32>>>((const int*)eidx);
    k_zero<<<1184, 256>>>();
    k_node1<<<444, 128>>>(nodes, gvWh, gvMu, gvWm, gvWb, lng, lnb,
                          gveWh, geWh, gveMu, geMu, gveWm, geWm);
    k_edge<<<592, 128>>>(edges, eidx, gveWh, gveMu, gveWm, gveWb,
                         geWh, geMu, geWm, geWb, out_e);
    k_node2<<<296, 256>>>(lng, lnb);
    k_node3<<<1184, 256>>>(out);
}